// round 14
// baseline (speedup 1.0000x reference)
#include <cuda_runtime.h>
#include <cuda_fp16.h>
#include <cstdint>

// ---------------------------------------------------------------------------
// QuantLinearTensorWise: y[8192,16384] = x[8192,4096] @ (W*scale)^T + bias
// Portable tensor-core path (compute_103 target): ldmatrix + mma.sync m16n8k16.
// R13: R12 (persistent CTAs + cross-tile pipeline, tensor=82%) with:
//      - GRID=148 (exact SM fill, no dead CTA churn)
//      - convert kernel: 512 thr, 2 independent chunks/thr (higher MLP)
//      - scale hoisted out of the tile loop, __ldg bias
// ---------------------------------------------------------------------------

#define IN_F   4096
#define OUT_F  16384
#define NROWS  8192

#define BM 128
#define BN 256
#define BK 64
#define STAGES 4
#define THREADS 256
#define K_ITERS (IN_F / BK)        // 64  (multiple of STAGES)
#define TILES_M (NROWS / BM)       // 64
#define TILES_N (OUT_F / BN)       // 64
#define NTILES (TILES_M * TILES_N) // 4096
#define GROUP_M 8
#define GRID 148

// padded smem rows: 64 halves data + 8 halves pad = 72 halves = 144 bytes
#define SROW 72
#define TILE_A_BYTES (BM * SROW * 2)               // 18432
#define TILE_B_BYTES (BN * SROW * 2)               // 36864
#define STAGE_BYTES (TILE_A_BYTES + TILE_B_BYTES)  // 55296
#define SMEM_STAGES (STAGES * STAGE_BYTES)         // 221184
#define SMEM_TOTAL (SMEM_STAGES + 16)              // + work-index slot

// fp16 scratch + work counter
__device__ __half g_xh[(size_t)NROWS * IN_F];
__device__ __half g_wh[(size_t)OUT_F * IN_F];
__device__ unsigned int g_tile_ctr;

// ---------------------------------------------------------------------------
// Fused conversion kernel: 512 thr, 2 chunks per thread per role.
// Blocks [0, XB2): x.  [XB2, XB2+WB2): W.  Also resets the tile counter.
// ---------------------------------------------------------------------------
#define NX4 (NROWS * IN_F / 4)     // 8388608
#define NW4 (OUT_F * IN_F / 4)     // 16777216
#define CVT_T 512
#define XB2 (NX4 / (CVT_T * 2))    // 8192 blocks
#define WB2 (NW4 / (CVT_T * 2))    // 16384 blocks

__global__ void k_convert_fused(const float4* __restrict__ x,
                                const int4* __restrict__ w) {
    int b = blockIdx.x;
    if (b == 0 && threadIdx.x == 0) g_tile_ctr = 0u;
    if (b < XB2) {
        int base = b * (CVT_T * 2) + threadIdx.x;
        __half2* o = reinterpret_cast<__half2*>(g_xh);
#pragma unroll
        for (int j = 0; j < 2; j++) {
            int i = base + j * CVT_T;
            float4 v = x[i];
            o[2 * i]     = __floats2half2_rn(v.x, v.y);
            o[2 * i + 1] = __floats2half2_rn(v.z, v.w);
        }
    } else {
        int base = (b - XB2) * (CVT_T * 2) + threadIdx.x;
        __half2* o = reinterpret_cast<__half2*>(g_wh);
#pragma unroll
        for (int j = 0; j < 2; j++) {
            int i = base + j * CVT_T;
            int4 v = w[i];
            o[2 * i]     = __halves2half2(__int2half_rn(v.x), __int2half_rn(v.y));
            o[2 * i + 1] = __halves2half2(__int2half_rn(v.z), __int2half_rn(v.w));
        }
    }
}

// ---------------------------------------------------------------------------
// PTX helpers (portable sm_80+)
// ---------------------------------------------------------------------------
__device__ __forceinline__ uint32_t smem_u32(const void* p) {
    uint32_t a;
    asm("{ .reg .u64 t; cvta.to.shared.u64 t, %1; cvt.u32.u64 %0, t; }"
        : "=r"(a) : "l"(p));
    return a;
}

__device__ __forceinline__ void cp_async16(uint32_t dst, const void* src) {
    asm volatile("cp.async.cg.shared.global [%0], [%1], 16;"
                 :: "r"(dst), "l"(src) : "memory");
}

__device__ __forceinline__ void cp_commit() {
    asm volatile("cp.async.commit_group;" ::: "memory");
}

__device__ __forceinline__ void cp_wait2() {
    asm volatile("cp.async.wait_group 2;" ::: "memory");
}

__device__ __forceinline__ void cp_wait_all() {
    asm volatile("cp.async.wait_group 0;" ::: "memory");
}

__device__ __forceinline__ void ldmx4(uint32_t* r, uint32_t addr) {
    asm volatile("ldmatrix.sync.aligned.m8n8.x4.shared.b16 {%0,%1,%2,%3}, [%4];"
                 : "=r"(r[0]), "=r"(r[1]), "=r"(r[2]), "=r"(r[3]) : "r"(addr));
}

__device__ __forceinline__ void mma16816(float* d, const uint32_t* a,
                                         const uint32_t* b) {
    asm volatile(
        "mma.sync.aligned.m16n8k16.row.col.f32.f16.f16.f32 "
        "{%0,%1,%2,%3}, {%4,%5,%6,%7}, {%8,%9}, {%0,%1,%2,%3};"
        : "+f"(d[0]), "+f"(d[1]), "+f"(d[2]), "+f"(d[3])
        : "r"(a[0]), "r"(a[1]), "r"(a[2]), "r"(a[3]), "r"(b[0]), "r"(b[1]));
}

// tile id -> (m0, n0) with GROUP_M raster swizzle
__device__ __forceinline__ void tile_coords(int t, int* m0, int* n0) {
    int per_group = GROUP_M * TILES_N;
    int g = t / per_group;
    int rem = t - g * per_group;
    int mt = g * GROUP_M + (rem % GROUP_M);
    int nt = rem / GROUP_M;
    *m0 = mt * BM;
    *n0 = nt * BN;
}

// ---------------------------------------------------------------------------
// Stage loads, split into three slices (A, B-half0, B-half1)
// ---------------------------------------------------------------------------
__device__ __forceinline__ void load_A(uint32_t stage_base, int kt,
                                       int m0, int tid) {
    int k0 = kt * BK;
#pragma unroll
    for (int h = 0; h < 4; h++) {
        int idx = tid + h * THREADS;
        int row = idx >> 3, c = idx & 7;
        uint32_t off = (uint32_t)(row * (SROW * 2) + c * 16);
        cp_async16(stage_base + off,
                   g_xh + (size_t)(m0 + row) * IN_F + k0 + c * 8);
    }
}

__device__ __forceinline__ void load_B(uint32_t stage_base, int kt,
                                       int n0, int tid, int half) {
    int k0 = kt * BK;
    uint32_t bB = stage_base + TILE_A_BYTES;
#pragma unroll
    for (int h = 0; h < 4; h++) {
        int idx = tid + (half * 4 + h) * THREADS;
        int row = idx >> 3, c = idx & 7;
        uint32_t off = (uint32_t)(row * (SROW * 2) + c * 16);
        cp_async16(bB + off, g_wh + (size_t)(n0 + row) * IN_F + k0 + c * 8);
    }
}

// ---------------------------------------------------------------------------
// Persistent GEMM kernel: warp grid 2(M) x 4(N), warp tile 64x64,
// cross-tile frag + stage pipeline
// ---------------------------------------------------------------------------
__global__ void __launch_bounds__(THREADS, 1)
gemm_hmma_kernel(const float* __restrict__ scale_p,
                 const float* __restrict__ bias,
                 float* __restrict__ out) {
    extern __shared__ char smem[];
    uint32_t sb = smem_u32(smem);
    volatile int* t_slot = (volatile int*)(smem + SMEM_STAGES);
    int tid = threadIdx.x;
    int lane = tid & 31;
    int warp = tid >> 5;     // 0..7
    int wm = warp & 1;       // M dir: 64 rows
    int wn = warp >> 1;      // N dir: 0..3, 64 cols

    float scl = *scale_p;    // hoisted: one LDG per CTA

    // ldmatrix lane address components (halves)
    int ar = (lane & 7) + ((lane >> 3) & 1) * 8;
    int ac = (lane >> 4) * 8;
    int bn_l = (lane & 7) + (lane >> 4) * 8;
    int bk_l = ((lane >> 3) & 1) * 8;

    uint32_t a_off[4], b_off[4];
#pragma unroll
    for (int mi = 0; mi < 4; mi++)
        a_off[mi] = (uint32_t)(((wm * 64 + mi * 16 + ar) * SROW + ac) * 2);
#pragma unroll
    for (int nj2 = 0; nj2 < 4; nj2++)
        b_off[nj2] = (uint32_t)(((wn * 64 + nj2 * 16 + bn_l) * SROW + bk_l) * 2);

    // grab first tile
    if (tid == 0) t_slot[0] = (int)atomicAdd(&g_tile_ctr, 1u);
    __syncthreads();
    int t_cur = t_slot[0];
    if (t_cur >= NTILES) return;
    int m0, n0;
    tile_coords(t_cur, &m0, &n0);

    float acc[4][8][4];
#pragma unroll
    for (int i = 0; i < 4; i++)
#pragma unroll
        for (int j = 0; j < 8; j++)
#pragma unroll
            for (int r = 0; r < 4; r++) acc[i][j][r] = 0.0f;

    // prologue: fill stages 0..2 with (t_cur, kt=0..2)
#pragma unroll
    for (int s = 0; s < STAGES - 1; s++) {
        uint32_t st = sb + s * STAGE_BYTES;
        load_A(st, s, m0, tid);
        load_B(st, s, n0, tid, 0);
        load_B(st, s, n0, tid, 1);
        cp_commit();
    }

    // grab next tile (visible after the sync below)
    if (tid == 0) t_slot[0] = (int)atomicAdd(&g_tile_ctr, 1u);

    uint32_t a[2][4][4], b[2][4][4];

    cp_wait2();
    __syncthreads();
    int t_next = t_slot[0];
    int mn0 = 0, nn0 = 0;
    if (t_next < NTILES) tile_coords(t_next, &mn0, &nn0);

    uint32_t aS = sb, bS = sb + TILE_A_BYTES;
#pragma unroll
    for (int mi = 0; mi < 4; mi++) ldmx4(a[0][mi], aS + a_off[mi]);
#pragma unroll
    for (int nj2 = 0; nj2 < 4; nj2++) ldmx4(b[0][nj2], bS + b_off[nj2]);

    while (true) {
        for (int kt = 0; kt < K_ITERS; kt++) {
            int nx = kt + STAGES - 1;              // 3..66
            bool nx_in_cur = nx < K_ITERS;
            bool do_load = nx_in_cur || (t_next < NTILES);
            int lm0 = nx_in_cur ? m0 : mn0;
            int ln0 = nx_in_cur ? n0 : nn0;
            int lkt = nx_in_cur ? nx : nx - K_ITERS;
            uint32_t nstg = sb + (nx & 3) * STAGE_BYTES;

#pragma unroll
            for (int ks = 0; ks < 4; ks++) {
                int cur = ks & 1, nxt = cur ^ 1;

                if (ks == 0) {
                    if (do_load) load_A(nstg, lkt, lm0, tid);
                } else if (ks == 1) {
                    if (do_load) load_B(nstg, lkt, ln0, tid, 0);
                } else if (ks == 2) {
                    if (do_load) load_B(nstg, lkt, ln0, tid, 1);
                    cp_commit();   // one group per kt (may be empty)
                }

                if (ks < 3) {
                    uint32_t ko = (uint32_t)((ks + 1) * 16 * 2);
#pragma unroll
                    for (int mi = 0; mi < 4; mi++)
                        ldmx4(a[nxt][mi], aS + a_off[mi] + ko);
#pragma unroll
                    for (int nj2 = 0; nj2 < 4; nj2++)
                        ldmx4(b[nxt][nj2], bS + b_off[nj2] + ko);
                } else {
                    bool have_next = (kt + 1 < K_ITERS) || (t_next < NTILES);
                    if (have_next) {
                        cp_wait2();
                        __syncthreads();
                        uint32_t stg = sb + ((kt + 1) & 3) * STAGE_BYTES;
                        aS = stg;
                        bS = stg + TILE_A_BYTES;
#pragma unroll
                        for (int mi = 0; mi < 4; mi++)
                            ldmx4(a[nxt][mi], aS + a_off[mi]);
#pragma unroll
                        for (int nj2 = 0; nj2 < 4; nj2++)
                            ldmx4(b[nxt][nj2], bS + b_off[nj2]);
                    }
                }

#pragma unroll
                for (int mi = 0; mi < 4; mi++) {
#pragma unroll
                    for (int nj = 0; nj < 8; nj++)
                        mma16816(acc[mi][nj], a[cur][mi], &b[cur][nj >> 1][(nj & 1) * 2]);
                }
            }
        }

        // epilogue for t_cur (runs under the next tile's in-flight cp.asyncs)
        {
            int gid = lane >> 2, tig = lane & 3;
#pragma unroll
            for (int mi = 0; mi < 4; mi++) {
                int row0 = m0 + wm * 64 + mi * 16 + gid;
#pragma unroll
                for (int nj = 0; nj < 8; nj++) {
                    int col = n0 + wn * 64 + nj * 8 + 2 * tig;
                    float2 bb = __ldg((const float2*)&bias[col]);
                    float2 v0, v1;
                    v0.x = fmaf(acc[mi][nj][0], scl, bb.x);
                    v0.y = fmaf(acc[mi][nj][1], scl, bb.y);
                    v1.x = fmaf(acc[mi][nj][2], scl, bb.x);
                    v1.y = fmaf(acc[mi][nj][3], scl, bb.y);
                    *(float2*)&out[(size_t)row0 * OUT_F + col] = v0;
                    *(float2*)&out[(size_t)(row0 + 8) * OUT_F + col] = v1;
                    acc[mi][nj][0] = 0.0f;
                    acc[mi][nj][1] = 0.0f;
                    acc[mi][nj][2] = 0.0f;
                    acc[mi][nj][3] = 0.0f;
                }
            }
        }

        if (t_next >= NTILES) break;
        t_cur = t_next;
        m0 = mn0;
        n0 = nn0;
        if (tid == 0) t_slot[0] = (int)atomicAdd(&g_tile_ctr, 1u);
        __syncthreads();
        t_next = t_slot[0];
        if (t_next < NTILES) tile_coords(t_next, &mn0, &nn0);
    }

    cp_wait_all();   // drain pending cp.asyncs before CTA exit
}

// ---------------------------------------------------------------------------
// Launch
// ---------------------------------------------------------------------------
extern "C" void kernel_launch(void* const* d_in, const int* in_sizes, int n_in,
                              void* d_out, int out_size) {
    const float* x     = (const float*)d_in[0];
    const int*   w     = (const int*)d_in[1];
    const float* scale = (const float*)d_in[2];
    const float* bias  = (const float*)d_in[3];
    float* out = (float*)d_out;

    cudaFuncSetAttribute(gemm_hmma_kernel,
                         cudaFuncAttributeMaxDynamicSharedMemorySize, SMEM_TOTAL);

    k_convert_fused<<<XB2 + WB2, CVT_T>>>((const float4*)x, (const int4*)w);
    gemm_hmma_kernel<<<GRID, THREADS, SMEM_TOTAL>>>(scale, bias, out);
}

// round 15
// speedup vs baseline: 1.0759x; 1.0759x over previous
#include <cuda_runtime.h>
#include <cuda_fp16.h>
#include <cstdint>

// ---------------------------------------------------------------------------
// QuantLinearTensorWise: y[8192,16384] = x[8192,4096] @ (W*scale)^T + bias
// Portable tensor-core path (compute_103 target): ldmatrix + mma.sync m16n8k16.
// R14: revert to R12 (best: 2294us; GRID=512 — GB300 has 152 SMs, 148 starved
//      it). ONE change vs R12: convert kernel uses 4 independent chunks/thread
//      (MLP=4) to lift its 68%-of-HBM to ~79%.
// ---------------------------------------------------------------------------

#define IN_F   4096
#define OUT_F  16384
#define NROWS  8192

#define BM 128
#define BN 256
#define BK 64
#define STAGES 4
#define THREADS 256
#define K_ITERS (IN_F / BK)        // 64  (multiple of STAGES)
#define TILES_M (NROWS / BM)       // 64
#define TILES_N (OUT_F / BN)       // 64
#define NTILES (TILES_M * TILES_N) // 4096
#define GROUP_M 8
#define GRID 512

// padded smem rows: 64 halves data + 8 halves pad = 72 halves = 144 bytes
#define SROW 72
#define TILE_A_BYTES (BM * SROW * 2)               // 18432
#define TILE_B_BYTES (BN * SROW * 2)               // 36864
#define STAGE_BYTES (TILE_A_BYTES + TILE_B_BYTES)  // 55296
#define SMEM_STAGES (STAGES * STAGE_BYTES)         // 221184
#define SMEM_TOTAL (SMEM_STAGES + 16)              // + work-index slot

// fp16 scratch + work counter
__device__ __half g_xh[(size_t)NROWS * IN_F];
__device__ __half g_wh[(size_t)OUT_F * IN_F];
__device__ unsigned int g_tile_ctr;

// ---------------------------------------------------------------------------
// Fused conversion kernel: 256 thr, 4 independent chunks/thread (MLP=4).
// Blocks [0, XB4): x.  [XB4, XB4+WB4): W.  Also resets the tile counter.
// ---------------------------------------------------------------------------
#define NX4 (NROWS * IN_F / 4)     // 8388608
#define NW4 (OUT_F * IN_F / 4)     // 16777216
#define XB4 (NX4 / (256 * 4))      // 8192 blocks
#define WB4 (NW4 / (256 * 4))      // 16384 blocks

__global__ void k_convert_fused(const float4* __restrict__ x,
                                const int4* __restrict__ w) {
    int b = blockIdx.x;
    if (b == 0 && threadIdx.x == 0) g_tile_ctr = 0u;
    if (b < XB4) {
        int base = b * (256 * 4) + threadIdx.x;
        __half2* o = reinterpret_cast<__half2*>(g_xh);
        float4 v[4];
#pragma unroll
        for (int j = 0; j < 4; j++) v[j] = x[base + j * 256];
#pragma unroll
        for (int j = 0; j < 4; j++) {
            int i = base + j * 256;
            o[2 * i]     = __floats2half2_rn(v[j].x, v[j].y);
            o[2 * i + 1] = __floats2half2_rn(v[j].z, v[j].w);
        }
    } else {
        int base = (b - XB4) * (256 * 4) + threadIdx.x;
        __half2* o = reinterpret_cast<__half2*>(g_wh);
        int4 v[4];
#pragma unroll
        for (int j = 0; j < 4; j++) v[j] = w[base + j * 256];
#pragma unroll
        for (int j = 0; j < 4; j++) {
            int i = base + j * 256;
            o[2 * i]     = __halves2half2(__int2half_rn(v[j].x), __int2half_rn(v[j].y));
            o[2 * i + 1] = __halves2half2(__int2half_rn(v[j].z), __int2half_rn(v[j].w));
        }
    }
}

// ---------------------------------------------------------------------------
// PTX helpers (portable sm_80+)
// ---------------------------------------------------------------------------
__device__ __forceinline__ uint32_t smem_u32(const void* p) {
    uint32_t a;
    asm("{ .reg .u64 t; cvta.to.shared.u64 t, %1; cvt.u32.u64 %0, t; }"
        : "=r"(a) : "l"(p));
    return a;
}

__device__ __forceinline__ void cp_async16(uint32_t dst, const void* src) {
    asm volatile("cp.async.cg.shared.global [%0], [%1], 16;"
                 :: "r"(dst), "l"(src) : "memory");
}

__device__ __forceinline__ void cp_commit() {
    asm volatile("cp.async.commit_group;" ::: "memory");
}

__device__ __forceinline__ void cp_wait2() {
    asm volatile("cp.async.wait_group 2;" ::: "memory");
}

__device__ __forceinline__ void cp_wait_all() {
    asm volatile("cp.async.wait_group 0;" ::: "memory");
}

__device__ __forceinline__ void ldmx4(uint32_t* r, uint32_t addr) {
    asm volatile("ldmatrix.sync.aligned.m8n8.x4.shared.b16 {%0,%1,%2,%3}, [%4];"
                 : "=r"(r[0]), "=r"(r[1]), "=r"(r[2]), "=r"(r[3]) : "r"(addr));
}

__device__ __forceinline__ void mma16816(float* d, const uint32_t* a,
                                         const uint32_t* b) {
    asm volatile(
        "mma.sync.aligned.m16n8k16.row.col.f32.f16.f16.f32 "
        "{%0,%1,%2,%3}, {%4,%5,%6,%7}, {%8,%9}, {%0,%1,%2,%3};"
        : "+f"(d[0]), "+f"(d[1]), "+f"(d[2]), "+f"(d[3])
        : "r"(a[0]), "r"(a[1]), "r"(a[2]), "r"(a[3]), "r"(b[0]), "r"(b[1]));
}

// tile id -> (m0, n0) with GROUP_M raster swizzle
__device__ __forceinline__ void tile_coords(int t, int* m0, int* n0) {
    int per_group = GROUP_M * TILES_N;
    int g = t / per_group;
    int rem = t - g * per_group;
    int mt = g * GROUP_M + (rem % GROUP_M);
    int nt = rem / GROUP_M;
    *m0 = mt * BM;
    *n0 = nt * BN;
}

// ---------------------------------------------------------------------------
// Stage loads, split into three slices (A, B-half0, B-half1)
// ---------------------------------------------------------------------------
__device__ __forceinline__ void load_A(uint32_t stage_base, int kt,
                                       int m0, int tid) {
    int k0 = kt * BK;
#pragma unroll
    for (int h = 0; h < 4; h++) {
        int idx = tid + h * THREADS;
        int row = idx >> 3, c = idx & 7;
        uint32_t off = (uint32_t)(row * (SROW * 2) + c * 16);
        cp_async16(stage_base + off,
                   g_xh + (size_t)(m0 + row) * IN_F + k0 + c * 8);
    }
}

__device__ __forceinline__ void load_B(uint32_t stage_base, int kt,
                                       int n0, int tid, int half) {
    int k0 = kt * BK;
    uint32_t bB = stage_base + TILE_A_BYTES;
#pragma unroll
    for (int h = 0; h < 4; h++) {
        int idx = tid + (half * 4 + h) * THREADS;
        int row = idx >> 3, c = idx & 7;
        uint32_t off = (uint32_t)(row * (SROW * 2) + c * 16);
        cp_async16(bB + off, g_wh + (size_t)(n0 + row) * IN_F + k0 + c * 8);
    }
}

// ---------------------------------------------------------------------------
// Persistent GEMM kernel: warp grid 2(M) x 4(N), warp tile 64x64,
// cross-tile frag + stage pipeline
// ---------------------------------------------------------------------------
__global__ void __launch_bounds__(THREADS, 1)
gemm_hmma_kernel(const float* __restrict__ scale_p,
                 const float* __restrict__ bias,
                 float* __restrict__ out) {
    extern __shared__ char smem[];
    uint32_t sb = smem_u32(smem);
    volatile int* t_slot = (volatile int*)(smem + SMEM_STAGES);
    int tid = threadIdx.x;
    int lane = tid & 31;
    int warp = tid >> 5;     // 0..7
    int wm = warp & 1;       // M dir: 64 rows
    int wn = warp >> 1;      // N dir: 0..3, 64 cols

    // ldmatrix lane address components (halves)
    int ar = (lane & 7) + ((lane >> 3) & 1) * 8;
    int ac = (lane >> 4) * 8;
    int bn_l = (lane & 7) + (lane >> 4) * 8;
    int bk_l = ((lane >> 3) & 1) * 8;

    uint32_t a_off[4], b_off[4];
#pragma unroll
    for (int mi = 0; mi < 4; mi++)
        a_off[mi] = (uint32_t)(((wm * 64 + mi * 16 + ar) * SROW + ac) * 2);
#pragma unroll
    for (int nj2 = 0; nj2 < 4; nj2++)
        b_off[nj2] = (uint32_t)(((wn * 64 + nj2 * 16 + bn_l) * SROW + bk_l) * 2);

    // grab first tile
    if (tid == 0) t_slot[0] = (int)atomicAdd(&g_tile_ctr, 1u);
    __syncthreads();
    int t_cur = t_slot[0];
    if (t_cur >= NTILES) return;
    int m0, n0;
    tile_coords(t_cur, &m0, &n0);

    float acc[4][8][4];
#pragma unroll
    for (int i = 0; i < 4; i++)
#pragma unroll
        for (int j = 0; j < 8; j++)
#pragma unroll
            for (int r = 0; r < 4; r++) acc[i][j][r] = 0.0f;

    // prologue: fill stages 0..2 with (t_cur, kt=0..2)
#pragma unroll
    for (int s = 0; s < STAGES - 1; s++) {
        uint32_t st = sb + s * STAGE_BYTES;
        load_A(st, s, m0, tid);
        load_B(st, s, n0, tid, 0);
        load_B(st, s, n0, tid, 1);
        cp_commit();
    }

    // grab next tile (visible after the sync below)
    if (tid == 0) t_slot[0] = (int)atomicAdd(&g_tile_ctr, 1u);

    uint32_t a[2][4][4], b[2][4][4];

    cp_wait2();
    __syncthreads();
    int t_next = t_slot[0];
    int mn0 = 0, nn0 = 0;
    if (t_next < NTILES) tile_coords(t_next, &mn0, &nn0);

    uint32_t aS = sb, bS = sb + TILE_A_BYTES;
#pragma unroll
    for (int mi = 0; mi < 4; mi++) ldmx4(a[0][mi], aS + a_off[mi]);
#pragma unroll
    for (int nj2 = 0; nj2 < 4; nj2++) ldmx4(b[0][nj2], bS + b_off[nj2]);

    while (true) {
        for (int kt = 0; kt < K_ITERS; kt++) {
            int nx = kt + STAGES - 1;              // 3..66
            bool nx_in_cur = nx < K_ITERS;
            bool do_load = nx_in_cur || (t_next < NTILES);
            int lm0 = nx_in_cur ? m0 : mn0;
            int ln0 = nx_in_cur ? n0 : nn0;
            int lkt = nx_in_cur ? nx : nx - K_ITERS;
            uint32_t nstg = sb + (nx & 3) * STAGE_BYTES;

#pragma unroll
            for (int ks = 0; ks < 4; ks++) {
                int cur = ks & 1, nxt = cur ^ 1;

                if (ks == 0) {
                    if (do_load) load_A(nstg, lkt, lm0, tid);
                } else if (ks == 1) {
                    if (do_load) load_B(nstg, lkt, ln0, tid, 0);
                } else if (ks == 2) {
                    if (do_load) load_B(nstg, lkt, ln0, tid, 1);
                    cp_commit();   // one group per kt (may be empty)
                }

                if (ks < 3) {
                    uint32_t ko = (uint32_t)((ks + 1) * 16 * 2);
#pragma unroll
                    for (int mi = 0; mi < 4; mi++)
                        ldmx4(a[nxt][mi], aS + a_off[mi] + ko);
#pragma unroll
                    for (int nj2 = 0; nj2 < 4; nj2++)
                        ldmx4(b[nxt][nj2], bS + b_off[nj2] + ko);
                } else {
                    bool have_next = (kt + 1 < K_ITERS) || (t_next < NTILES);
                    if (have_next) {
                        cp_wait2();
                        __syncthreads();
                        uint32_t stg = sb + ((kt + 1) & 3) * STAGE_BYTES;
                        aS = stg;
                        bS = stg + TILE_A_BYTES;
#pragma unroll
                        for (int mi = 0; mi < 4; mi++)
                            ldmx4(a[nxt][mi], aS + a_off[mi]);
#pragma unroll
                        for (int nj2 = 0; nj2 < 4; nj2++)
                            ldmx4(b[nxt][nj2], bS + b_off[nj2]);
                    }
                }

#pragma unroll
                for (int mi = 0; mi < 4; mi++) {
#pragma unroll
                    for (int nj = 0; nj < 8; nj++)
                        mma16816(acc[mi][nj], a[cur][mi], &b[cur][nj >> 1][(nj & 1) * 2]);
                }
            }
        }

        // epilogue for t_cur (runs under the next tile's in-flight cp.asyncs)
        {
            float scl = *scale_p;
            int gid = lane >> 2, tig = lane & 3;
#pragma unroll
            for (int mi = 0; mi < 4; mi++) {
                int row0 = m0 + wm * 64 + mi * 16 + gid;
#pragma unroll
                for (int nj = 0; nj < 8; nj++) {
                    int col = n0 + wn * 64 + nj * 8 + 2 * tig;
                    float2 bb = *(const float2*)&bias[col];
                    float2 v0, v1;
                    v0.x = fmaf(acc[mi][nj][0], scl, bb.x);
                    v0.y = fmaf(acc[mi][nj][1], scl, bb.y);
                    v1.x = fmaf(acc[mi][nj][2], scl, bb.x);
                    v1.y = fmaf(acc[mi][nj][3], scl, bb.y);
                    *(float2*)&out[(size_t)row0 * OUT_F + col] = v0;
                    *(float2*)&out[(size_t)(row0 + 8) * OUT_F + col] = v1;
                    acc[mi][nj][0] = 0.0f;
                    acc[mi][nj][1] = 0.0f;
                    acc[mi][nj][2] = 0.0f;
                    acc[mi][nj][3] = 0.0f;
                }
            }
        }

        if (t_next >= NTILES) break;
        t_cur = t_next;
        m0 = mn0;
        n0 = nn0;
        if (tid == 0) t_slot[0] = (int)atomicAdd(&g_tile_ctr, 1u);
        __syncthreads();
        t_next = t_slot[0];
        if (t_next < NTILES) tile_coords(t_next, &mn0, &nn0);
    }

    cp_wait_all();   // drain pending cp.asyncs before CTA exit
}

// ---------------------------------------------------------------------------
// Launch
// ---------------------------------------------------------------------------
extern "C" void kernel_launch(void* const* d_in, const int* in_sizes, int n_in,
                              void* d_out, int out_size) {
    const float* x     = (const float*)d_in[0];
    const int*   w     = (const int*)d_in[1];
    const float* scale = (const float*)d_in[2];
    const float* bias  = (const float*)d_in[3];
    float* out = (float*)d_out;

    cudaFuncSetAttribute(gemm_hmma_kernel,
                         cudaFuncAttributeMaxDynamicSharedMemorySize, SMEM_TOTAL);

    k_convert_fused<<<XB4 + WB4, 256>>>((const float4*)x, (const int4*)w);
    gemm_hmma_kernel<<<GRID, THREADS, SMEM_TOTAL>>>(scale, bias, out);
}